// round 7
// baseline (speedup 1.0000x reference)
#include <cuda_runtime.h>
#include <cuda_bf16.h>
#include <cstdint>

// GaussianModel preprocess — TMA-staged, 512-pt tiles (2 pts/thread), evict_first.
// Output layout (fp32): [xyz (N*3) | cov3d (N*9) | rgb (N*3) | opacity (N*1)] = 16N

#define C0 0.28209479177387814f
#define C1 0.4886025119029199f

__device__ __forceinline__ float sigmoidf_(float v) {
    return __fdividef(1.0f, 1.0f + __expf(-v));
}

__device__ __forceinline__ uint32_t smem_u32(const void* p) {
    uint32_t a;
    asm("{ .reg .u64 t; cvta.to.shared.u64 t, %1; cvt.u32.u64 %0, t; }"
        : "=r"(a) : "l"(p));
    return a;
}

__device__ __forceinline__ uint64_t evict_first_policy() {
    uint64_t pol;
    asm("createpolicy.fractional.L2::evict_first.b64 %0, 1.0;" : "=l"(pol));
    return pol;
}

__device__ __forceinline__ void bulk_g2s(uint32_t smem_addr, const void* gmem,
                                         uint32_t bytes, uint32_t mbar, uint64_t pol) {
    asm volatile(
        "cp.async.bulk.shared::cta.global.mbarrier::complete_tx::bytes.L2::cache_hint"
        " [%0], [%1], %2, [%3], %4;"
        :: "r"(smem_addr), "l"(gmem), "r"(bytes), "r"(mbar), "l"(pol) : "memory");
}

__device__ __forceinline__ void bulk_s2g(void* gmem, uint32_t smem_addr,
                                         uint32_t bytes, uint64_t pol) {
    asm volatile(
        "cp.async.bulk.global.shared::cta.bulk_group.L2::cache_hint [%0], [%1], %2, %3;"
        :: "l"(gmem), "r"(smem_addr), "r"(bytes), "l"(pol) : "memory");
}

__device__ __forceinline__ void mbar_init(uint32_t mbar, uint32_t count) {
    asm volatile("mbarrier.init.shared.b64 [%0], %1;" :: "r"(mbar), "r"(count) : "memory");
}

__device__ __forceinline__ void mbar_expect_tx(uint32_t mbar, uint32_t bytes) {
    asm volatile("mbarrier.arrive.expect_tx.shared.b64 _, [%0], %1;"
                 :: "r"(mbar), "r"(bytes) : "memory");
}

__device__ __forceinline__ void mbar_wait(uint32_t mbar, uint32_t parity) {
    asm volatile(
        "{\n\t"
        ".reg .pred P1;\n\t"
        "WAIT_LOOP_%=:\n\t"
        "mbarrier.try_wait.parity.acquire.cta.shared::cta.b64 P1, [%0], %1, 0x989680;\n\t"
        "@P1 bra.uni WAIT_DONE_%=;\n\t"
        "bra.uni WAIT_LOOP_%=;\n\t"
        "WAIT_DONE_%=:\n\t"
        "}"
        :: "r"(mbar), "r"(parity) : "memory");
}

// per-point math shared by both paths
__device__ __forceinline__ void compute_cov(float4 q, float s0, float s1, float s2,
                                            float& c00, float& c01, float& c02,
                                            float& c11, float& c12, float& c22) {
    float inv = rsqrtf(fmaxf(q.x * q.x + q.y * q.y + q.z * q.z + q.w * q.w, 1e-24f));
    float qr = q.x * inv, qx = q.y * inv, qy = q.z * inv, qz = q.w * inv;

    float M00 = (1.0f - 2.0f * (qy * qy + qz * qz)) * s0;
    float M01 = (2.0f * (qx * qy - qr * qz)) * s1;
    float M02 = (2.0f * (qx * qz + qr * qy)) * s2;
    float M10 = (2.0f * (qx * qy + qr * qz)) * s0;
    float M11 = (1.0f - 2.0f * (qx * qx + qz * qz)) * s1;
    float M12 = (2.0f * (qy * qz - qr * qx)) * s2;
    float M20 = (2.0f * (qx * qz - qr * qy)) * s0;
    float M21 = (2.0f * (qy * qz + qr * qx)) * s1;
    float M22 = (1.0f - 2.0f * (qx * qx + qy * qy)) * s2;

    c00 = M00 * M00 + M01 * M01 + M02 * M02;
    c01 = M00 * M10 + M01 * M11 + M02 * M12;
    c02 = M00 * M20 + M01 * M21 + M02 * M22;
    c11 = M10 * M10 + M11 * M11 + M12 * M12;
    c12 = M10 * M20 + M11 * M21 + M12 * M22;
    c22 = M20 * M20 + M21 * M21 + M22 * M22;
}

__global__ __launch_bounds__(256, 5)
void gaussian_kernel(const float* __restrict__ view_dirs,
                     const float* __restrict__ xyz,
                     const float* __restrict__ scale_log,
                     const float* __restrict__ rot_quat,
                     const float* __restrict__ opacity_logit,
                     const float* __restrict__ sh_coeffs,
                     float* __restrict__ out,
                     int n, int aligned)
{
    constexpr int T = 512;            // points per CTA (2 per thread)
    const int base = blockIdx.x * T;
    int m = n - base;
    if (m > T) m = T;
    const int t = threadIdx.x;

    float* out_xyz = out;
    float* out_cov = out + (size_t)n * 3;
    float* out_rgb = out + (size_t)n * 12;
    float* out_opa = out + (size_t)n * 15;

    // ---------------- fallback (tail tile or misaligned buffers) ----------------
    if (m != T || !aligned) {
        for (int p = t; p < m; p += 256) {
            int i = base + p;
            out_xyz[(size_t)i * 3 + 0] = xyz[(size_t)i * 3 + 0];
            out_xyz[(size_t)i * 3 + 1] = xyz[(size_t)i * 3 + 1];
            out_xyz[(size_t)i * 3 + 2] = xyz[(size_t)i * 3 + 2];

            float dx = view_dirs[(size_t)i * 3 + 0];
            float dy = view_dirs[(size_t)i * 3 + 1];
            float dz = view_dirs[(size_t)i * 3 + 2];
            const float* sh = sh_coeffs + (size_t)i * 12;
            for (int c = 0; c < 3; c++) {
                out_rgb[(size_t)i * 3 + c] =
                    sigmoidf_(C0 * sh[c * 4 + 0] - C1 * dy * sh[c * 4 + 1]
                              + C1 * dz * sh[c * 4 + 2] - C1 * dx * sh[c * 4 + 3]);
            }
            out_opa[i] = sigmoidf_(opacity_logit[i]);

            float s0 = __expf(scale_log[(size_t)i * 3 + 0]);
            float s1 = __expf(scale_log[(size_t)i * 3 + 1]);
            float s2 = __expf(scale_log[(size_t)i * 3 + 2]);
            float4 q = make_float4(rot_quat[(size_t)i * 4 + 0], rot_quat[(size_t)i * 4 + 1],
                                   rot_quat[(size_t)i * 4 + 2], rot_quat[(size_t)i * 4 + 3]);
            float c00, c01, c02, c11, c12, c22;
            compute_cov(q, s0, s1, s2, c00, c01, c02, c11, c12, c22);
            float* cv = out_cov + (size_t)i * 9;
            cv[0] = c00; cv[1] = c01; cv[2] = c02;
            cv[3] = c01; cv[4] = c11; cv[5] = c12;
            cv[6] = c02; cv[7] = c12; cv[8] = c22;
        }
        return;
    }

    // ---------------- TMA path (full 512-pt tile) ----------------
    // smem floats: xyz[0,1536) vd[1536,3072) sl[3072,4608) sh[4608,10752)
    // output staging reuses: cov[1536,6144) rgb[6144,7680); xyz region untouched.
    __shared__ __align__(128) float s[10752];
    __shared__ __align__(8) uint64_t mbar_storage;

    float* s_xyz = s;
    float* s_vd  = s + 1536;
    float* s_sl  = s + 3072;
    float* s_sh  = s + 4608;
    const uint32_t mbar = smem_u32(&mbar_storage);
    const uint64_t pol = evict_first_policy();

    if (t == 0) mbar_init(mbar, 1);
    __syncthreads();

    if (t == 0) {
        constexpr uint32_t BYTES = 10752 * 4;  // 43008
        mbar_expect_tx(mbar, BYTES);
        bulk_g2s(smem_u32(s_sh),  sh_coeffs + (size_t)base * 12, 6144 * 4, mbar, pol);
        bulk_g2s(smem_u32(s_vd),  view_dirs + (size_t)base * 3,  1536 * 4, mbar, pol);
        bulk_g2s(smem_u32(s_sl),  scale_log + (size_t)base * 3,  1536 * 4, mbar, pol);
        bulk_g2s(smem_u32(s_xyz), xyz       + (size_t)base * 3,  1536 * 4, mbar, pol);
    }

    // overlap with TMA: quat + opacity via streaming LDG/STG (2 pts/thread)
    float4 q0 = __ldcs(reinterpret_cast<const float4*>(rot_quat) + base + t);
    float4 q1 = __ldcs(reinterpret_cast<const float4*>(rot_quat) + base + t + 256);
    __stcs(out_opa + base + t,       sigmoidf_(__ldcs(opacity_logit + base + t)));
    __stcs(out_opa + base + t + 256, sigmoidf_(__ldcs(opacity_logit + base + t + 256)));

    mbar_wait(mbar, 0);

    // xyz passthrough bounce (region [0,1536) never overwritten)
    if (t == 0) {
        bulk_s2g(out_xyz + (size_t)base * 3, smem_u32(s_xyz), 1536 * 4, pol);
    }

    // ---------------- compute (points t and t+256) ----------------
    float rr[2], gg[2], bb[2];
    float c00[2], c01[2], c02[2], c11[2], c12[2], c22[2];

    #pragma unroll
    for (int w = 0; w < 2; w++) {
        int p = t + w * 256;
        {
            float dx = s_vd[p * 3 + 0];
            float dy = s_vd[p * 3 + 1];
            float dz = s_vd[p * 3 + 2];
            const float4* sh4 = reinterpret_cast<const float4*>(s_sh);
            float4 shr = sh4[p * 3 + 0];
            float4 shg = sh4[p * 3 + 1];
            float4 shb = sh4[p * 3 + 2];
            rr[w] = sigmoidf_(C0 * shr.x - C1 * dy * shr.y + C1 * dz * shr.z - C1 * dx * shr.w);
            gg[w] = sigmoidf_(C0 * shg.x - C1 * dy * shg.y + C1 * dz * shg.z - C1 * dx * shg.w);
            bb[w] = sigmoidf_(C0 * shb.x - C1 * dy * shb.y + C1 * dz * shb.z - C1 * dx * shb.w);
        }
        float s0 = __expf(s_sl[p * 3 + 0]);
        float s1 = __expf(s_sl[p * 3 + 1]);
        float s2 = __expf(s_sl[p * 3 + 2]);
        compute_cov(w ? q1 : q0, s0, s1, s2,
                    c00[w], c01[w], c02[w], c11[w], c12[w], c22[w]);
    }
    __syncthreads();   // all input staging consumed

    // ---------------- stage outputs, TMA store ----------------
    float* s_cov = s + 1536;   // 4608 floats
    float* s_rgb = s + 6144;   // 1536 floats
    #pragma unroll
    for (int w = 0; w < 2; w++) {
        int p = t + w * 256;
        float* cv = s_cov + p * 9;
        cv[0] = c00[w]; cv[1] = c01[w]; cv[2] = c02[w];
        cv[3] = c01[w]; cv[4] = c11[w]; cv[5] = c12[w];
        cv[6] = c02[w]; cv[7] = c12[w]; cv[8] = c22[w];
        s_rgb[p * 3 + 0] = rr[w];
        s_rgb[p * 3 + 1] = gg[w];
        s_rgb[p * 3 + 2] = bb[w];
    }
    __syncthreads();

    if (t == 0) {
        asm volatile("fence.proxy.async.shared::cta;" ::: "memory");
        bulk_s2g(out_cov + (size_t)base * 9, smem_u32(s_cov), 4608 * 4, pol);
        bulk_s2g(out_rgb + (size_t)base * 3, smem_u32(s_rgb), 1536 * 4, pol);
        asm volatile("cp.async.bulk.commit_group;" ::: "memory");
        asm volatile("cp.async.bulk.wait_group.read 0;" ::: "memory");
    }
}

extern "C" void kernel_launch(void* const* d_in, const int* in_sizes, int n_in,
                              void* d_out, int out_size) {
    const float* view_dirs     = (const float*)d_in[0];
    const float* xyz           = (const float*)d_in[1];
    const float* scale_log     = (const float*)d_in[2];
    const float* rot_quat      = (const float*)d_in[3];
    const float* opacity_logit = (const float*)d_in[4];
    const float* sh_coeffs     = (const float*)d_in[5];
    float* out = (float*)d_out;

    int n = in_sizes[1] / 3;
    int aligned = ((n & 3) == 0);   // output segment bases 16B-aligned

    int blocks = (n + 511) / 512;
    gaussian_kernel<<<blocks, 256>>>(view_dirs, xyz, scale_log, rot_quat,
                                     opacity_logit, sh_coeffs, out, n, aligned);
}

// round 8
// speedup vs baseline: 1.0012x; 1.0012x over previous
#include <cuda_runtime.h>
#include <cuda_bf16.h>
#include <cstdint>

// GaussianModel preprocess — TMA-staged (256-pt tiles) + early LDG overlap.
// Output layout (fp32): [xyz (N*3) | cov3d (N*9) | rgb (N*3) | opacity (N*1)] = 16N

#define C0 0.28209479177387814f
#define C1 0.4886025119029199f

__device__ __forceinline__ float sigmoidf_(float v) {
    return __fdividef(1.0f, 1.0f + __expf(-v));
}

__device__ __forceinline__ uint32_t smem_u32(const void* p) {
    uint32_t a;
    asm("{ .reg .u64 t; cvta.to.shared.u64 t, %1; cvt.u32.u64 %0, t; }"
        : "=r"(a) : "l"(p));
    return a;
}

__device__ __forceinline__ uint64_t evict_first_policy() {
    uint64_t pol;
    asm("createpolicy.fractional.L2::evict_first.b64 %0, 1.0;" : "=l"(pol));
    return pol;
}

__device__ __forceinline__ void bulk_g2s(uint32_t smem_addr, const void* gmem,
                                         uint32_t bytes, uint32_t mbar, uint64_t pol) {
    asm volatile(
        "cp.async.bulk.shared::cta.global.mbarrier::complete_tx::bytes.L2::cache_hint"
        " [%0], [%1], %2, [%3], %4;"
        :: "r"(smem_addr), "l"(gmem), "r"(bytes), "r"(mbar), "l"(pol) : "memory");
}

__device__ __forceinline__ void bulk_s2g(void* gmem, uint32_t smem_addr,
                                         uint32_t bytes, uint64_t pol) {
    asm volatile(
        "cp.async.bulk.global.shared::cta.bulk_group.L2::cache_hint [%0], [%1], %2, %3;"
        :: "l"(gmem), "r"(smem_addr), "r"(bytes), "l"(pol) : "memory");
}

__device__ __forceinline__ void mbar_init(uint32_t mbar, uint32_t count) {
    asm volatile("mbarrier.init.shared.b64 [%0], %1;" :: "r"(mbar), "r"(count) : "memory");
}

__device__ __forceinline__ void mbar_expect_tx(uint32_t mbar, uint32_t bytes) {
    asm volatile("mbarrier.arrive.expect_tx.shared.b64 _, [%0], %1;"
                 :: "r"(mbar), "r"(bytes) : "memory");
}

__device__ __forceinline__ void mbar_wait(uint32_t mbar, uint32_t parity) {
    asm volatile(
        "{\n\t"
        ".reg .pred P1;\n\t"
        "WAIT_LOOP_%=:\n\t"
        "mbarrier.try_wait.parity.acquire.cta.shared::cta.b64 P1, [%0], %1, 0x989680;\n\t"
        "@P1 bra.uni WAIT_DONE_%=;\n\t"
        "bra.uni WAIT_LOOP_%=;\n\t"
        "WAIT_DONE_%=:\n\t"
        "}"
        :: "r"(mbar), "r"(parity) : "memory");
}

__device__ __forceinline__ void compute_cov(float4 q, float s0, float s1, float s2,
                                            float& c00, float& c01, float& c02,
                                            float& c11, float& c12, float& c22) {
    float inv = rsqrtf(fmaxf(q.x * q.x + q.y * q.y + q.z * q.z + q.w * q.w, 1e-24f));
    float qr = q.x * inv, qx = q.y * inv, qy = q.z * inv, qz = q.w * inv;

    float M00 = (1.0f - 2.0f * (qy * qy + qz * qz)) * s0;
    float M01 = (2.0f * (qx * qy - qr * qz)) * s1;
    float M02 = (2.0f * (qx * qz + qr * qy)) * s2;
    float M10 = (2.0f * (qx * qy + qr * qz)) * s0;
    float M11 = (1.0f - 2.0f * (qx * qx + qz * qz)) * s1;
    float M12 = (2.0f * (qy * qz - qr * qx)) * s2;
    float M20 = (2.0f * (qx * qz - qr * qy)) * s0;
    float M21 = (2.0f * (qy * qz + qr * qx)) * s1;
    float M22 = (1.0f - 2.0f * (qx * qx + qy * qy)) * s2;

    c00 = M00 * M00 + M01 * M01 + M02 * M02;
    c01 = M00 * M10 + M01 * M11 + M02 * M12;
    c02 = M00 * M20 + M01 * M21 + M02 * M22;
    c11 = M10 * M10 + M11 * M11 + M12 * M12;
    c12 = M10 * M20 + M11 * M21 + M12 * M22;
    c22 = M20 * M20 + M21 * M21 + M22 * M22;
}

__global__ __launch_bounds__(256, 8)
void gaussian_kernel(const float* __restrict__ view_dirs,
                     const float* __restrict__ xyz,
                     const float* __restrict__ scale_log,
                     const float* __restrict__ rot_quat,
                     const float* __restrict__ opacity_logit,
                     const float* __restrict__ sh_coeffs,
                     float* __restrict__ out,
                     int n, int aligned)
{
    constexpr int T = 256;
    const int base = blockIdx.x * T;
    int m = n - base;
    if (m > T) m = T;
    const int t = threadIdx.x;

    float* out_xyz = out;
    float* out_cov = out + (size_t)n * 3;
    float* out_rgb = out + (size_t)n * 12;
    float* out_opa = out + (size_t)n * 15;

    // ---------------- fallback (tail tile or misaligned buffers) ----------------
    if (m != T || !aligned) {
        if (t < m) {
            int i = base + t;
            out_xyz[(size_t)i * 3 + 0] = xyz[(size_t)i * 3 + 0];
            out_xyz[(size_t)i * 3 + 1] = xyz[(size_t)i * 3 + 1];
            out_xyz[(size_t)i * 3 + 2] = xyz[(size_t)i * 3 + 2];

            float dx = view_dirs[(size_t)i * 3 + 0];
            float dy = view_dirs[(size_t)i * 3 + 1];
            float dz = view_dirs[(size_t)i * 3 + 2];
            const float* sh = sh_coeffs + (size_t)i * 12;
            for (int c = 0; c < 3; c++) {
                out_rgb[(size_t)i * 3 + c] =
                    sigmoidf_(C0 * sh[c * 4 + 0] - C1 * dy * sh[c * 4 + 1]
                              + C1 * dz * sh[c * 4 + 2] - C1 * dx * sh[c * 4 + 3]);
            }
            out_opa[i] = sigmoidf_(opacity_logit[i]);

            float s0 = __expf(scale_log[(size_t)i * 3 + 0]);
            float s1 = __expf(scale_log[(size_t)i * 3 + 1]);
            float s2 = __expf(scale_log[(size_t)i * 3 + 2]);
            float4 q = make_float4(rot_quat[(size_t)i * 4 + 0], rot_quat[(size_t)i * 4 + 1],
                                   rot_quat[(size_t)i * 4 + 2], rot_quat[(size_t)i * 4 + 3]);
            float c00, c01, c02, c11, c12, c22;
            compute_cov(q, s0, s1, s2, c00, c01, c02, c11, c12, c22);
            float* cv = out_cov + (size_t)i * 9;
            cv[0] = c00; cv[1] = c01; cv[2] = c02;
            cv[3] = c01; cv[4] = c11; cv[5] = c12;
            cv[6] = c02; cv[7] = c12; cv[8] = c22;
        }
        return;
    }

    // ---------------- TMA path (full tile) ----------------
    // smem floats: xyz[0,768) vd[768,1536) sl[1536,2304) sh[2304,5376)
    // output staging reuses: cov[768,3072) rgb[3072,3840); xyz region untouched.
    __shared__ __align__(128) float s[5376];
    __shared__ __align__(8) uint64_t mbar_storage;

    float* s_xyz = s;
    float* s_vd  = s + 768;
    float* s_sl  = s + 1536;
    float* s_sh  = s + 2304;
    const uint32_t mbar = smem_u32(&mbar_storage);
    const uint64_t pol = evict_first_policy();

    // issue the per-thread LDGs FIRST — in flight before any barrier
    float4 q = __ldcs(reinterpret_cast<const float4*>(rot_quat) + base + t);
    float ol = __ldcs(opacity_logit + base + t);

    if (t == 0) mbar_init(mbar, 1);
    __syncthreads();

    if (t == 0) {
        constexpr uint32_t BYTES = (768 + 768 + 768 + 3072) * 4;  // 21504
        mbar_expect_tx(mbar, BYTES);
        bulk_g2s(smem_u32(s_sh),  sh_coeffs + (size_t)base * 12, 3072 * 4, mbar, pol);
        bulk_g2s(smem_u32(s_vd),  view_dirs + (size_t)base * 3,  768 * 4,  mbar, pol);
        bulk_g2s(smem_u32(s_sl),  scale_log + (size_t)base * 3,  768 * 4,  mbar, pol);
        bulk_g2s(smem_u32(s_xyz), xyz       + (size_t)base * 3,  768 * 4,  mbar, pol);
    }

    // opacity: compute + store while TMA fills smem
    __stcs(out_opa + base + t, sigmoidf_(ol));

    mbar_wait(mbar, 0);

    // xyz passthrough bounce (region [0,768) never overwritten)
    if (t == 0) {
        bulk_s2g(out_xyz + (size_t)base * 3, smem_u32(s_xyz), 768 * 4, pol);
    }

    // ---------------- compute ----------------
    float r, g, b, c00, c01, c02, c11, c12, c22;
    {
        float dx = s_vd[t * 3 + 0];
        float dy = s_vd[t * 3 + 1];
        float dz = s_vd[t * 3 + 2];
        const float4* sh4 = reinterpret_cast<const float4*>(s_sh);
        float4 shr = sh4[t * 3 + 0];
        float4 shg = sh4[t * 3 + 1];
        float4 shb = sh4[t * 3 + 2];
        r = sigmoidf_(C0 * shr.x - C1 * dy * shr.y + C1 * dz * shr.z - C1 * dx * shr.w);
        g = sigmoidf_(C0 * shg.x - C1 * dy * shg.y + C1 * dz * shg.z - C1 * dx * shg.w);
        b = sigmoidf_(C0 * shb.x - C1 * dy * shb.y + C1 * dz * shb.z - C1 * dx * shb.w);
    }
    {
        float s0 = __expf(s_sl[t * 3 + 0]);
        float s1 = __expf(s_sl[t * 3 + 1]);
        float s2 = __expf(s_sl[t * 3 + 2]);
        compute_cov(q, s0, s1, s2, c00, c01, c02, c11, c12, c22);
    }
    __syncthreads();   // all input staging consumed

    // ---------------- stage outputs, TMA store ----------------
    float* s_cov = s + 768;    // 2304 floats
    float* s_rgb = s + 3072;   // 768 floats
    {
        float* cv = s_cov + t * 9;
        cv[0] = c00; cv[1] = c01; cv[2] = c02;
        cv[3] = c01; cv[4] = c11; cv[5] = c12;
        cv[6] = c02; cv[7] = c12; cv[8] = c22;
        s_rgb[t * 3 + 0] = r;
        s_rgb[t * 3 + 1] = g;
        s_rgb[t * 3 + 2] = b;
    }
    __syncthreads();

    if (t == 0) {
        asm volatile("fence.proxy.async.shared::cta;" ::: "memory");
        bulk_s2g(out_cov + (size_t)base * 9, smem_u32(s_cov), 2304 * 4, pol);
        bulk_s2g(out_rgb + (size_t)base * 3, smem_u32(s_rgb), 768 * 4, pol);
        asm volatile("cp.async.bulk.commit_group;" ::: "memory");
        asm volatile("cp.async.bulk.wait_group.read 0;" ::: "memory");
    }
}

extern "C" void kernel_launch(void* const* d_in, const int* in_sizes, int n_in,
                              void* d_out, int out_size) {
    const float* view_dirs     = (const float*)d_in[0];
    const float* xyz           = (const float*)d_in[1];
    const float* scale_log     = (const float*)d_in[2];
    const float* rot_quat      = (const float*)d_in[3];
    const float* opacity_logit = (const float*)d_in[4];
    const float* sh_coeffs     = (const float*)d_in[5];
    float* out = (float*)d_out;

    int n = in_sizes[1] / 3;
    int aligned = ((n & 3) == 0);   // output segment bases 16B-aligned

    int blocks = (n + 255) / 256;
    gaussian_kernel<<<blocks, 256>>>(view_dirs, xyz, scale_log, rot_quat,
                                     opacity_logit, sh_coeffs, out, n, aligned);
}

// round 9
// speedup vs baseline: 1.0084x; 1.0072x over previous
#include <cuda_runtime.h>
#include <cuda_bf16.h>
#include <cstdint>

// GaussianModel preprocess — TMA-staged, per-warp store epilogue.
// Output layout (fp32): [xyz (N*3) | cov3d (N*9) | rgb (N*3) | opacity (N*1)] = 16N

#define C0 0.28209479177387814f
#define C1 0.4886025119029199f

__device__ __forceinline__ float sigmoidf_(float v) {
    return __fdividef(1.0f, 1.0f + __expf(-v));
}

__device__ __forceinline__ uint32_t smem_u32(const void* p) {
    uint32_t a;
    asm("{ .reg .u64 t; cvta.to.shared.u64 t, %1; cvt.u32.u64 %0, t; }"
        : "=r"(a) : "l"(p));
    return a;
}

__device__ __forceinline__ uint64_t evict_first_policy() {
    uint64_t pol;
    asm("createpolicy.fractional.L2::evict_first.b64 %0, 1.0;" : "=l"(pol));
    return pol;
}

__device__ __forceinline__ void bulk_g2s(uint32_t smem_addr, const void* gmem,
                                         uint32_t bytes, uint32_t mbar, uint64_t pol) {
    asm volatile(
        "cp.async.bulk.shared::cta.global.mbarrier::complete_tx::bytes.L2::cache_hint"
        " [%0], [%1], %2, [%3], %4;"
        :: "r"(smem_addr), "l"(gmem), "r"(bytes), "r"(mbar), "l"(pol) : "memory");
}

__device__ __forceinline__ void bulk_s2g(void* gmem, uint32_t smem_addr,
                                         uint32_t bytes, uint64_t pol) {
    asm volatile(
        "cp.async.bulk.global.shared::cta.bulk_group.L2::cache_hint [%0], [%1], %2, %3;"
        :: "l"(gmem), "r"(smem_addr), "r"(bytes), "l"(pol) : "memory");
}

__device__ __forceinline__ void mbar_init(uint32_t mbar, uint32_t count) {
    asm volatile("mbarrier.init.shared.b64 [%0], %1;" :: "r"(mbar), "r"(count) : "memory");
}

__device__ __forceinline__ void mbar_expect_tx(uint32_t mbar, uint32_t bytes) {
    asm volatile("mbarrier.arrive.expect_tx.shared.b64 _, [%0], %1;"
                 :: "r"(mbar), "r"(bytes) : "memory");
}

__device__ __forceinline__ void mbar_wait(uint32_t mbar, uint32_t parity) {
    asm volatile(
        "{\n\t"
        ".reg .pred P1;\n\t"
        "WAIT_LOOP_%=:\n\t"
        "mbarrier.try_wait.parity.acquire.cta.shared::cta.b64 P1, [%0], %1, 0x989680;\n\t"
        "@P1 bra.uni WAIT_DONE_%=;\n\t"
        "bra.uni WAIT_LOOP_%=;\n\t"
        "WAIT_DONE_%=:\n\t"
        "}"
        :: "r"(mbar), "r"(parity) : "memory");
}

__device__ __forceinline__ void compute_cov(float4 q, float s0, float s1, float s2,
                                            float& c00, float& c01, float& c02,
                                            float& c11, float& c12, float& c22) {
    float inv = rsqrtf(fmaxf(q.x * q.x + q.y * q.y + q.z * q.z + q.w * q.w, 1e-24f));
    float qr = q.x * inv, qx = q.y * inv, qy = q.z * inv, qz = q.w * inv;

    float M00 = (1.0f - 2.0f * (qy * qy + qz * qz)) * s0;
    float M01 = (2.0f * (qx * qy - qr * qz)) * s1;
    float M02 = (2.0f * (qx * qz + qr * qy)) * s2;
    float M10 = (2.0f * (qx * qy + qr * qz)) * s0;
    float M11 = (1.0f - 2.0f * (qx * qx + qz * qz)) * s1;
    float M12 = (2.0f * (qy * qz - qr * qx)) * s2;
    float M20 = (2.0f * (qx * qz - qr * qy)) * s0;
    float M21 = (2.0f * (qy * qz + qr * qx)) * s1;
    float M22 = (1.0f - 2.0f * (qx * qx + qy * qy)) * s2;

    c00 = M00 * M00 + M01 * M01 + M02 * M02;
    c01 = M00 * M10 + M01 * M11 + M02 * M12;
    c02 = M00 * M20 + M01 * M21 + M02 * M22;
    c11 = M10 * M10 + M11 * M11 + M12 * M12;
    c12 = M10 * M20 + M11 * M21 + M12 * M22;
    c22 = M20 * M20 + M21 * M21 + M22 * M22;
}

__global__ __launch_bounds__(256, 6)
void gaussian_kernel(const float* __restrict__ view_dirs,
                     const float* __restrict__ xyz,
                     const float* __restrict__ scale_log,
                     const float* __restrict__ rot_quat,
                     const float* __restrict__ opacity_logit,
                     const float* __restrict__ sh_coeffs,
                     float* __restrict__ out,
                     int n, int aligned)
{
    constexpr int T = 256;
    const int base = blockIdx.x * T;
    int m = n - base;
    if (m > T) m = T;
    const int t = threadIdx.x;
    const int warp = t >> 5;
    const int lane = t & 31;

    float* out_xyz = out;
    float* out_cov = out + (size_t)n * 3;
    float* out_rgb = out + (size_t)n * 12;
    float* out_opa = out + (size_t)n * 15;

    // ---------------- fallback (tail tile or misaligned buffers) ----------------
    if (m != T || !aligned) {
        if (t < m) {
            int i = base + t;
            out_xyz[(size_t)i * 3 + 0] = xyz[(size_t)i * 3 + 0];
            out_xyz[(size_t)i * 3 + 1] = xyz[(size_t)i * 3 + 1];
            out_xyz[(size_t)i * 3 + 2] = xyz[(size_t)i * 3 + 2];

            float dx = view_dirs[(size_t)i * 3 + 0];
            float dy = view_dirs[(size_t)i * 3 + 1];
            float dz = view_dirs[(size_t)i * 3 + 2];
            const float* sh = sh_coeffs + (size_t)i * 12;
            for (int c = 0; c < 3; c++) {
                out_rgb[(size_t)i * 3 + c] =
                    sigmoidf_(C0 * sh[c * 4 + 0] - C1 * dy * sh[c * 4 + 1]
                              + C1 * dz * sh[c * 4 + 2] - C1 * dx * sh[c * 4 + 3]);
            }
            out_opa[i] = sigmoidf_(opacity_logit[i]);

            float s0 = __expf(scale_log[(size_t)i * 3 + 0]);
            float s1 = __expf(scale_log[(size_t)i * 3 + 1]);
            float s2 = __expf(scale_log[(size_t)i * 3 + 2]);
            float4 q = make_float4(rot_quat[(size_t)i * 4 + 0], rot_quat[(size_t)i * 4 + 1],
                                   rot_quat[(size_t)i * 4 + 2], rot_quat[(size_t)i * 4 + 3]);
            float c00, c01, c02, c11, c12, c22;
            compute_cov(q, s0, s1, s2, c00, c01, c02, c11, c12, c22);
            float* cv = out_cov + (size_t)i * 9;
            cv[0] = c00; cv[1] = c01; cv[2] = c02;
            cv[3] = c01; cv[4] = c11; cv[5] = c12;
            cv[6] = c02; cv[7] = c12; cv[8] = c22;
        }
        return;
    }

    // ---------------- TMA path (full tile) ----------------
    // inputs:  xyz[0,768) vd[768,1536) sl[1536,2304) sh[2304,5376)
    // outputs: cov[5376,7680) rgb[7680,8448)   (dedicated — no reuse barrier needed)
    __shared__ __align__(128) float s[8448];
    __shared__ __align__(8) uint64_t mbar_storage;

    float* s_xyz = s;
    float* s_vd  = s + 768;
    float* s_sl  = s + 1536;
    float* s_sh  = s + 2304;
    float* s_cov = s + 5376;
    float* s_rgb = s + 7680;
    const uint32_t mbar = smem_u32(&mbar_storage);
    const uint64_t pol = evict_first_policy();

    // issue the per-thread LDGs FIRST — in flight before any barrier
    float4 q = __ldcs(reinterpret_cast<const float4*>(rot_quat) + base + t);
    float ol = __ldcs(opacity_logit + base + t);

    if (t == 0) mbar_init(mbar, 1);
    __syncthreads();

    if (t == 0) {
        constexpr uint32_t BYTES = (768 + 768 + 768 + 3072) * 4;  // 21504
        mbar_expect_tx(mbar, BYTES);
        bulk_g2s(smem_u32(s_sh),  sh_coeffs + (size_t)base * 12, 3072 * 4, mbar, pol);
        bulk_g2s(smem_u32(s_vd),  view_dirs + (size_t)base * 3,  768 * 4,  mbar, pol);
        bulk_g2s(smem_u32(s_sl),  scale_log + (size_t)base * 3,  768 * 4,  mbar, pol);
        bulk_g2s(smem_u32(s_xyz), xyz       + (size_t)base * 3,  768 * 4,  mbar, pol);
    }

    // opacity: compute + store while TMA fills smem
    __stcs(out_opa + base + t, sigmoidf_(ol));

    mbar_wait(mbar, 0);

    // xyz passthrough bounce (region never overwritten)
    if (t == 0) {
        bulk_s2g(out_xyz + (size_t)base * 3, smem_u32(s_xyz), 768 * 4, pol);
    }

    // ---------------- compute ----------------
    float r, g, b, c00, c01, c02, c11, c12, c22;
    {
        float dx = s_vd[t * 3 + 0];
        float dy = s_vd[t * 3 + 1];
        float dz = s_vd[t * 3 + 2];
        const float4* sh4 = reinterpret_cast<const float4*>(s_sh);
        float4 shr = sh4[t * 3 + 0];
        float4 shg = sh4[t * 3 + 1];
        float4 shb = sh4[t * 3 + 2];
        r = sigmoidf_(C0 * shr.x - C1 * dy * shr.y + C1 * dz * shr.z - C1 * dx * shr.w);
        g = sigmoidf_(C0 * shg.x - C1 * dy * shg.y + C1 * dz * shg.z - C1 * dx * shg.w);
        b = sigmoidf_(C0 * shb.x - C1 * dy * shb.y + C1 * dz * shb.z - C1 * dx * shb.w);
    }
    {
        float s0 = __expf(s_sl[t * 3 + 0]);
        float s1 = __expf(s_sl[t * 3 + 1]);
        float s2 = __expf(s_sl[t * 3 + 2]);
        compute_cov(q, s0, s1, s2, c00, c01, c02, c11, c12, c22);
    }

    // ---------------- per-warp staged stores (no block barrier) ----------------
    {
        float* cv = s_cov + t * 9;
        cv[0] = c00; cv[1] = c01; cv[2] = c02;
        cv[3] = c01; cv[4] = c11; cv[5] = c12;
        cv[6] = c02; cv[7] = c12; cv[8] = c22;
        s_rgb[t * 3 + 0] = r;
        s_rgb[t * 3 + 1] = g;
        s_rgb[t * 3 + 2] = b;
    }
    __syncwarp();

    if (lane == 0) {
        asm volatile("fence.proxy.async.shared::cta;" ::: "memory");
        // this warp's cov chunk: 32 pts * 9 floats = 288 floats = 1152 B (16B aligned)
        bulk_s2g(out_cov + (size_t)base * 9 + warp * 288,
                 smem_u32(s_cov + warp * 288), 288 * 4, pol);
        // this warp's rgb chunk: 32 pts * 3 floats = 96 floats = 384 B
        bulk_s2g(out_rgb + (size_t)base * 3 + warp * 96,
                 smem_u32(s_rgb + warp * 96), 96 * 4, pol);
        asm volatile("cp.async.bulk.commit_group;" ::: "memory");
        asm volatile("cp.async.bulk.wait_group.read 0;" ::: "memory");
    }
}

extern "C" void kernel_launch(void* const* d_in, const int* in_sizes, int n_in,
                              void* d_out, int out_size) {
    const float* view_dirs     = (const float*)d_in[0];
    const float* xyz           = (const float*)d_in[1];
    const float* scale_log     = (const float*)d_in[2];
    const float* rot_quat      = (const float*)d_in[3];
    const float* opacity_logit = (const float*)d_in[4];
    const float* sh_coeffs     = (const float*)d_in[5];
    float* out = (float*)d_out;

    int n = in_sizes[1] / 3;
    int aligned = ((n & 3) == 0);   // output segment bases 16B-aligned

    int blocks = (n + 255) / 256;
    gaussian_kernel<<<blocks, 256>>>(view_dirs, xyz, scale_log, rot_quat,
                                     opacity_logit, sh_coeffs, out, n, aligned);
}